// round 9
// baseline (speedup 1.0000x reference)
#include <cuda_runtime.h>

#define BN   4
#define NF   8
#define CC   8
#define NPIX (512 * 512)
#define NG   (NPIX / 4)        // 65536 groups (of 4 pixels) per image

#define GPB  512               // groups per block (whole slice prefetched)
#define BX   (NG / GPB)        // 128 blocks per image
#define THR  256               // 2 groups per thread
#define P2_TOTAL (BX * BN)

#define SLICE_B   (GPB * 16)               // 8192 B per feature slice / labels
#define STAGE_B   (SLICE_B * (NF + 1))     // 73728 B data
#define SMEM_DYN  (STAGE_B + 16)           // + mbarrier
#define TX_BYTES  STAGE_B

typedef unsigned long long ULL;

struct Scratch {
    float sums[BN][CC][NF];
    float counts[BN][CC];
    float dist[BN];
    unsigned int ticket;
};
__device__ Scratch g_s;

// ---------------- PTX helpers ----------------
__device__ __forceinline__ unsigned sm32(const void* p) {
    unsigned r;
    asm("{ .reg .u64 t; cvta.to.shared.u64 t, %1; cvt.u32.u64 %0, t; }"
        : "=r"(r) : "l"(p));
    return r;
}
__device__ __forceinline__ void mbar_init(unsigned a, int cnt) {
    asm volatile("mbarrier.init.shared.b64 [%0], %1;" :: "r"(a), "r"(cnt) : "memory");
}
__device__ __forceinline__ void mbar_expect(unsigned a, unsigned bytes) {
    asm volatile("mbarrier.arrive.expect_tx.shared.b64 _, [%0], %1;"
                 :: "r"(a), "r"(bytes) : "memory");
}
__device__ __forceinline__ void mbar_wait(unsigned a, unsigned ph) {
    unsigned done;
    asm volatile(
        "{ .reg .pred p;\n\t"
        "mbarrier.try_wait.parity.acquire.cta.shared::cta.b64 p, [%1], %2;\n\t"
        "selp.b32 %0, 1, 0, p; }"
        : "=r"(done) : "r"(a), "r"(ph) : "memory");
    while (!done) {
        asm volatile(
            "{ .reg .pred p;\n\t"
            "mbarrier.try_wait.parity.acquire.cta.shared::cta.b64 p, [%1], %2, 0x989680;\n\t"
            "selp.b32 %0, 1, 0, p; }"
            : "=r"(done) : "r"(a), "r"(ph) : "memory");
    }
}
__device__ __forceinline__ void bulk_g2s(unsigned dst, const void* src,
                                         unsigned bytes, unsigned mbar) {
    asm volatile(
        "cp.async.bulk.shared::cluster.global.mbarrier::complete_tx::bytes "
        "[%0], [%1], %2, [%3];"
        :: "r"(dst), "l"(src), "r"(bytes), "r"(mbar) : "memory");
}
// Issue the block's whole slice: 8 pred slices + labels, one mbarrier.
__device__ __forceinline__ void issue_slice(unsigned dst, const char* predb,
                                            const char* tgtb, int g0,
                                            unsigned mbar) {
#pragma unroll
    for (int f = 0; f < NF; f++)
        bulk_g2s(dst + f * SLICE_B,
                 predb + (size_t)f * NPIX * 4 + (size_t)g0 * 16,
                 SLICE_B, mbar);
    bulk_g2s(dst + NF * SLICE_B, tgtb + (size_t)g0 * 16, SLICE_B, mbar);
}
__device__ __forceinline__ ULL fadd2(ULL a, ULL b) {
    ULL d;
    asm("add.rn.f32x2 %0, %1, %2;" : "=l"(d) : "l"(a), "l"(b));
    return d;
}
__device__ __forceinline__ ULL pack2(float lo, float hi) {
    ULL r;
    asm("mov.b64 %0, {%1, %2};" : "=l"(r) : "f"(lo), "f"(hi));
    return r;
}
__device__ __forceinline__ void unpack2(ULL v, float& lo, float& hi) {
    asm("mov.b64 {%0, %1}, %2;" : "=f"(lo), "=f"(hi) : "l"(v));
}
__device__ __forceinline__ void acc_if_eq(ULL& a0, ULL& a1, ULL& a2, ULL& a3,
                                          int& cnt, int lab, int c, int inc,
                                          ULL p0, ULL p1, ULL p2, ULL p3) {
    asm("{ .reg .pred p; setp.eq.s32 p, %5, %6;\n\t"
        "@p add.rn.f32x2 %0, %0, %8;\n\t"
        "@p add.rn.f32x2 %1, %1, %9;\n\t"
        "@p add.rn.f32x2 %2, %2, %10;\n\t"
        "@p add.rn.f32x2 %3, %3, %11;\n\t"
        "@p add.s32 %4, %4, %7; }"
        : "+l"(a0), "+l"(a1), "+l"(a2), "+l"(a3), "+r"(cnt)
        : "r"(lab), "r"(c), "r"(inc), "l"(p0), "l"(p1), "l"(p2), "l"(p3));
}
__device__ __forceinline__ float f4get(const float4 v, int i) {
    return i == 0 ? v.x : i == 1 ? v.y : i == 2 ? v.z : v.w;
}
__device__ __forceinline__ int i4get(const int4 v, int i) {
    return i == 0 ? v.x : i == 1 ? v.y : i == 2 ? v.z : v.w;
}

// ---------------------------------------------------------------------------
// Pass 1: full-prefetch TMA, per-cluster counts + feature sums.
// ---------------------------------------------------------------------------
__global__ void __launch_bounds__(THR) k_pass1(const float* __restrict__ pred,
                                               const int* __restrict__ tgt) {
    extern __shared__ char sm[];
    const int tid = threadIdx.x;
    const int b = blockIdx.y;
    const int g0 = blockIdx.x * GPB;
    const char* predb = (const char*)pred + (size_t)b * NF * NPIX * 4;
    const char* tgtb  = (const char*)tgt + (size_t)b * NPIX * 4;

    unsigned sbase = sm32(sm);
    unsigned mbar  = sbase + STAGE_B;
    if (tid == 0) mbar_init(mbar, 1);
    __syncthreads();
    if (tid == 0) {
        mbar_expect(mbar, TX_BYTES);
        issue_slice(sbase, predb, tgtb, g0, mbar);
    }

    ULL acc[CC][4];
    int cnta = 0, cntb = 0;
#pragma unroll
    for (int c = 0; c < CC; c++)
#pragma unroll
        for (int k = 0; k < 4; k++) acc[c][k] = 0ull;

    mbar_wait(mbar, 0);

#pragma unroll
    for (int it = 0; it < GPB / THR; it++) {
        int gl = tid + it * THR;
        int4 lab4 = ((const int4*)(sm + NF * SLICE_B))[gl];
        float4 v[NF];
#pragma unroll
        for (int f = 0; f < NF; f++)
            v[f] = ((const float4*)(sm + f * SLICE_B))[gl];

#pragma unroll
        for (int px = 0; px < 4; px++) {
            int lab = i4get(lab4, px);
            ULL pr0 = pack2(f4get(v[0], px), f4get(v[1], px));
            ULL pr1 = pack2(f4get(v[2], px), f4get(v[3], px));
            ULL pr2 = pack2(f4get(v[4], px), f4get(v[5], px));
            ULL pr3 = pack2(f4get(v[6], px), f4get(v[7], px));
#pragma unroll
            for (int c = 0; c < 4; c++)
                acc_if_eq(acc[c][0], acc[c][1], acc[c][2], acc[c][3],
                          cnta, lab, c, 1 << (8 * c), pr0, pr1, pr2, pr3);
#pragma unroll
            for (int c = 4; c < 8; c++)
                acc_if_eq(acc[c][0], acc[c][1], acc[c][2], acc[c][3],
                          cntb, lab, c, 1 << (8 * (c - 4)), pr0, pr1, pr2, pr3);
        }
    }

    int icnt[CC];
#pragma unroll
    for (int c = 0; c < 4; c++) {
        icnt[c]     = (cnta >> (8 * c)) & 0xFF;
        icnt[c + 4] = (cntb >> (8 * c)) & 0xFF;
    }
#pragma unroll
    for (int c = 0; c < CC; c++) {
#pragma unroll
        for (int k = 0; k < 4; k++) {
            ULL x = acc[c][k];
#pragma unroll
            for (int o = 16; o > 0; o >>= 1)
                x = fadd2(x, __shfl_down_sync(0xffffffffu, x, o));
            acc[c][k] = x;
        }
        int ic = icnt[c];
#pragma unroll
        for (int o = 16; o > 0; o >>= 1) ic += __shfl_down_sync(0xffffffffu, ic, o);
        icnt[c] = ic;
    }

    __shared__ float sw[8][72];
    int wid = tid >> 5, lane = tid & 31;
    if (lane == 0) {
#pragma unroll
        for (int c = 0; c < CC; c++) {
#pragma unroll
            for (int k = 0; k < 4; k++) {
                float lo, hi;
                unpack2(acc[c][k], lo, hi);
                sw[wid][c * NF + 2 * k]     = lo;
                sw[wid][c * NF + 2 * k + 1] = hi;
            }
            sw[wid][64 + c] = (float)icnt[c];
        }
    }
    __syncthreads();
    if (tid < 72) {
        float s = 0.f;
#pragma unroll
        for (int w = 0; w < 8; w++) s += sw[w][tid];
        if (tid < 64)
            atomicAdd(&((float*)g_s.sums)[b * 64 + tid], s);
        else
            atomicAdd(&g_s.counts[b][tid - 64], s);
    }
}

// ---------------------------------------------------------------------------
// Pass 2: full-prefetch TMA, hinge distance + fused finalize.
// ---------------------------------------------------------------------------
__global__ void __launch_bounds__(THR) k_pass2(const float* __restrict__ pred,
                                               const int* __restrict__ tgt,
                                               float* __restrict__ out) {
    extern __shared__ char sm[];
    const int tid = threadIdx.x;
    const int b = blockIdx.y;
    const int g0 = blockIdx.x * GPB;
    const char* predb = (const char*)pred + (size_t)b * NF * NPIX * 4;
    const char* tgtb  = (const char*)tgt + (size_t)b * NPIX * 4;

    unsigned sbase = sm32(sm);
    unsigned mbar  = sbase + STAGE_B;

    __shared__ float4 smean0[CC];   // features 0-3 per label
    __shared__ float4 smean1[CC];   // features 4-7 per label
    if (tid == 0) mbar_init(mbar, 1);
    __syncthreads();
    if (tid == 0) {
        mbar_expect(mbar, TX_BYTES);
        issue_slice(sbase, predb, tgtb, g0, mbar);
    }
    if (tid < 64) {
        int c = tid >> 3, f = tid & 7;
        float m = g_s.sums[b][c][f] / g_s.counts[b][c];
        float* base = (f < 4) ? (float*)&smean0[c] : (float*)&smean1[c];
        base[f & 3] = m;
    }
    __syncthreads();

    mbar_wait(mbar, 0);

    float local = 0.f;
#pragma unroll
    for (int it = 0; it < GPB / THR; it++) {
        int gl = tid + it * THR;
        int4 lab4 = ((const int4*)(sm + NF * SLICE_B))[gl];
        float4 v[NF];
#pragma unroll
        for (int f = 0; f < NF; f++)
            v[f] = ((const float4*)(sm + f * SLICE_B))[gl];

#pragma unroll
        for (int px = 0; px < 4; px++) {
            int lab = i4get(lab4, px);
            float4 m0 = smean0[lab];
            float4 m1 = smean1[lab];
            float d2 = 0.f, d;
            d = m0.x - f4get(v[0], px); d2 = fmaf(d, d, d2);
            d = m0.y - f4get(v[1], px); d2 = fmaf(d, d, d2);
            d = m0.z - f4get(v[2], px); d2 = fmaf(d, d, d2);
            d = m0.w - f4get(v[3], px); d2 = fmaf(d, d, d2);
            d = m1.x - f4get(v[4], px); d2 = fmaf(d, d, d2);
            d = m1.y - f4get(v[5], px); d2 = fmaf(d, d, d2);
            d = m1.z - f4get(v[6], px); d2 = fmaf(d, d, d2);
            d = m1.w - f4get(v[7], px); d2 = fmaf(d, d, d2);
            float tt = sqrtf(d2) - 0.5f;           // DELTA_V
            tt = fminf(fmaxf(tt, 0.f), 100000.f);
            local = fmaf(tt, tt, local);
        }
    }

#pragma unroll
    for (int o = 16; o > 0; o >>= 1)
        local += __shfl_down_sync(0xffffffffu, local, o);
    __shared__ float sred[8];
    int wid = tid >> 5, lane = tid & 31;
    if (lane == 0) sred[wid] = local;
    __syncthreads();
    if (tid == 0) {
        float s = 0.f;
#pragma unroll
        for (int w = 0; w < 8; w++) s += sred[w];
        atomicAdd(&g_s.dist[b], s);
    }

    // ---- last-block finalize ----
    __shared__ bool s_last;
    __threadfence();
    if (tid == 0) {
        unsigned int t = atomicAdd(&g_s.ticket, 1u);
        s_last = (t == P2_TOTAL - 1);
    }
    __syncthreads();
    if (!s_last) return;

    __shared__ float smu[BN][CC][NF];
    __shared__ float s_ldist[BN], s_lreg[BN], s_inv[BN];
    {
        int bb = tid >> 6, i = (tid >> 3) & 7, j = tid & 7;
        smu[bb][i][j] = __ldcg(&g_s.sums[bb][i][j]) / __ldcg(&g_s.counts[bb][i]);
    }
    if (tid < BN) { s_ldist[tid] = 0.f; s_lreg[tid] = 0.f; s_inv[tid] = 0.f; }
    __syncthreads();

    {
        int bb = tid >> 6, i = (tid >> 3) & 7, j = tid & 7;
        if (i != j) {
            float d2 = 0.f;
#pragma unroll
            for (int f = 0; f < NF; f++) {
                float d = smu[bb][i][f] - smu[bb][j][f];
                d2 = fmaf(d, d, d2);
            }
            float t = 3.0f - sqrtf(d2);            // 2 * DELTA_D
            t = fminf(fmaxf(t, 0.f), 100000.f);
            atomicAdd(&s_ldist[bb], t * t);
        } else {
            float d2 = 0.f;
#pragma unroll
            for (int f = 0; f < NF; f++)
                d2 = fmaf(smu[bb][i][f], smu[bb][i][f], d2);
            atomicAdd(&s_lreg[bb], sqrtf(d2));
            atomicAdd(&s_inv[bb], 1.0f / __ldcg(&g_s.counts[bb][i]));
        }
    }
    __syncthreads();

    if (tid == 0) {
        float total = 0.f;
#pragma unroll
        for (int q = 0; q < BN; q++) {
            float dq = __ldcg(&g_s.dist[q]);
            float l_var  = dq * s_inv[q] / (float)CC;
            float l_dist = s_ldist[q] / (float)(CC * (CC - 1));
            float l_reg  = s_lreg[q] / (float)CC;
            total += l_var + l_dist + 0.001f * l_reg;
        }
        out[0] = total / (float)BN;
    }
}

extern "C" void kernel_launch(void* const* d_in, const int* in_sizes, int n_in,
                              void* d_out, int out_size) {
    const float* pred = (const float*)d_in[0];
    const int*   tgt  = (const int*)d_in[1];
    float*       out  = (float*)d_out;
    (void)in_sizes; (void)n_in; (void)out_size;

    static bool attr_done = false;
    if (!attr_done) {
        cudaFuncSetAttribute(k_pass1, cudaFuncAttributeMaxDynamicSharedMemorySize,
                             SMEM_DYN);
        cudaFuncSetAttribute(k_pass2, cudaFuncAttributeMaxDynamicSharedMemorySize,
                             SMEM_DYN);
        attr_done = true;
    }

    void* scratch_ptr = nullptr;
    cudaGetSymbolAddress(&scratch_ptr, g_s);
    cudaMemsetAsync(scratch_ptr, 0, sizeof(Scratch));

    dim3 grid(BX, BN);
    k_pass1<<<grid, THR, SMEM_DYN>>>(pred, tgt);
    k_pass2<<<grid, THR, SMEM_DYN>>>(pred, tgt, out);
}

// round 10
// speedup vs baseline: 1.0447x; 1.0447x over previous
#include <cuda_runtime.h>
#include <cuda_fp16.h>

#define BN   4
#define NF   8
#define CC   8
#define NPIX (512 * 512)
#define NG   (NPIX / 4)          // 65536 groups (of 4 pixels) per image

#define P1_BX  256               // pass1: one group per thread
#define P1_THR 256
#define P2_BX  128               // pass2: two groups per thread (ILP)
#define P2_THR 256
#define P2_TOTAL (P2_BX * BN)

typedef unsigned long long ULL;

struct Scratch {
    float sums[BN][CC][NF];
    float counts[BN][CC];
    float dist[BN];
    unsigned int ticket;
};
__device__ Scratch g_s;                 // zero-init at load; self-reset each run
__device__ uint4 g_h[BN * 4 * NG];      // fp16 mirror: [img][pair][group] 16 MB

__device__ __forceinline__ ULL fadd2(ULL a, ULL b) {
    ULL d;
    asm("add.rn.f32x2 %0, %1, %2;" : "=l"(d) : "l"(a), "l"(b));
    return d;
}
__device__ __forceinline__ ULL pack2(float lo, float hi) {
    ULL r;
    asm("mov.b64 %0, {%1, %2};" : "=l"(r) : "f"(lo), "f"(hi));
    return r;
}
__device__ __forceinline__ void unpack2(ULL v, float& lo, float& hi) {
    asm("mov.b64 {%0, %1}, %2;" : "=f"(lo), "=f"(hi) : "l"(v));
}
__device__ __forceinline__ void acc_if_eq(ULL& a0, ULL& a1, ULL& a2, ULL& a3,
                                          int& cnt, int lab, int c, int inc,
                                          ULL p0, ULL p1, ULL p2, ULL p3) {
    asm("{ .reg .pred p; setp.eq.s32 p, %5, %6;\n\t"
        "@p add.rn.f32x2 %0, %0, %8;\n\t"
        "@p add.rn.f32x2 %1, %1, %9;\n\t"
        "@p add.rn.f32x2 %2, %2, %10;\n\t"
        "@p add.rn.f32x2 %3, %3, %11;\n\t"
        "@p add.s32 %4, %4, %7; }"
        : "+l"(a0), "+l"(a1), "+l"(a2), "+l"(a3), "+r"(cnt)
        : "r"(lab), "r"(c), "r"(inc), "l"(p0), "l"(p1), "l"(p2), "l"(p3));
}
__device__ __forceinline__ float f4get(const float4 v, int i) {
    return i == 0 ? v.x : i == 1 ? v.y : i == 2 ? v.z : v.w;
}
__device__ __forceinline__ int i4get(const int4 v, int i) {
    return i == 0 ? v.x : i == 1 ? v.y : i == 2 ? v.z : v.w;
}
__device__ __forceinline__ unsigned h2u(float a, float b) {
    __half2 h = __floats2half2_rn(a, b);
    return *reinterpret_cast<unsigned*>(&h);
}
__device__ __forceinline__ float2 u2f2(unsigned u) {
    return __half22float2(*reinterpret_cast<__half2*>(&u));
}

// ---------------------------------------------------------------------------
// Pass 1: per-cluster counts + sums; also writes fp16 mirror of pred.
// ---------------------------------------------------------------------------
__global__ void __launch_bounds__(P1_THR) k_pass1(const float* __restrict__ pred,
                                                  const int* __restrict__ tgt) {
    const int b = blockIdx.y;
    const float4* p = (const float4*)(pred + (size_t)b * NF * NPIX);
    const int4*   g = (const int4*)(tgt + (size_t)b * NPIX);
    const int tid = threadIdx.x;
    const int n = blockIdx.x * P1_THR + tid;   // exactly one group per thread

    int4 lab4 = g[n];
    float4 v[NF];
#pragma unroll
    for (int f = 0; f < NF; f++) v[f] = p[f * NG + n];

    // fp16 mirror, planar feature-pairs: g_h[(b*4 + k)*NG + n]
#pragma unroll
    for (int k = 0; k < 4; k++) {
        uint4 hq;
        hq.x = h2u(v[2 * k].x, v[2 * k + 1].x);
        hq.y = h2u(v[2 * k].y, v[2 * k + 1].y);
        hq.z = h2u(v[2 * k].z, v[2 * k + 1].z);
        hq.w = h2u(v[2 * k].w, v[2 * k + 1].w);
        g_h[((size_t)(b * 4 + k)) * NG + n] = hq;
    }

    ULL acc[CC][4];
    int cnta = 0, cntb = 0;
#pragma unroll
    for (int c = 0; c < CC; c++)
#pragma unroll
        for (int k = 0; k < 4; k++) acc[c][k] = 0ull;

#pragma unroll
    for (int px = 0; px < 4; px++) {
        int lab = i4get(lab4, px);
        ULL pr0 = pack2(f4get(v[0], px), f4get(v[1], px));
        ULL pr1 = pack2(f4get(v[2], px), f4get(v[3], px));
        ULL pr2 = pack2(f4get(v[4], px), f4get(v[5], px));
        ULL pr3 = pack2(f4get(v[6], px), f4get(v[7], px));
#pragma unroll
        for (int c = 0; c < 4; c++)
            acc_if_eq(acc[c][0], acc[c][1], acc[c][2], acc[c][3],
                      cnta, lab, c, 1 << (8 * c), pr0, pr1, pr2, pr3);
#pragma unroll
        for (int c = 4; c < 8; c++)
            acc_if_eq(acc[c][0], acc[c][1], acc[c][2], acc[c][3],
                      cntb, lab, c, 1 << (8 * (c - 4)), pr0, pr1, pr2, pr3);
    }

    int icnt[CC];
#pragma unroll
    for (int c = 0; c < 4; c++) {
        icnt[c]     = (cnta >> (8 * c)) & 0xFF;
        icnt[c + 4] = (cntb >> (8 * c)) & 0xFF;
    }
#pragma unroll
    for (int c = 0; c < CC; c++) {
#pragma unroll
        for (int k = 0; k < 4; k++) {
            ULL x = acc[c][k];
#pragma unroll
            for (int o = 16; o > 0; o >>= 1)
                x = fadd2(x, __shfl_down_sync(0xffffffffu, x, o));
            acc[c][k] = x;
        }
        int ic = icnt[c];
#pragma unroll
        for (int o = 16; o > 0; o >>= 1) ic += __shfl_down_sync(0xffffffffu, ic, o);
        icnt[c] = ic;
    }

    __shared__ float sw[8][72];
    int wid = tid >> 5, lane = tid & 31;
    if (lane == 0) {
#pragma unroll
        for (int c = 0; c < CC; c++) {
#pragma unroll
            for (int k = 0; k < 4; k++) {
                float lo, hi;
                unpack2(acc[c][k], lo, hi);
                sw[wid][c * NF + 2 * k]     = lo;
                sw[wid][c * NF + 2 * k + 1] = hi;
            }
            sw[wid][64 + c] = (float)icnt[c];
        }
    }
    __syncthreads();
    if (tid < 72) {
        float s = 0.f;
#pragma unroll
        for (int w = 0; w < 8; w++) s += sw[w][tid];
        if (tid < 64)
            atomicAdd(&((float*)g_s.sums)[b * 64 + tid], s);
        else
            atomicAdd(&g_s.counts[b][tid - 64], s);
    }
}

// ---------------------------------------------------------------------------
// Pass 2: hinge distance from fp16 mirror (half the bytes), ILP=2,
// fused finalize + scratch self-reset.
// ---------------------------------------------------------------------------
__global__ void __launch_bounds__(P2_THR) k_pass2(const int* __restrict__ tgt,
                                                  float* __restrict__ out) {
    const int b = blockIdx.y;
    const int tid = threadIdx.x;
    __shared__ float4 smean0[CC];   // features 0-3 per label
    __shared__ float4 smean1[CC];   // features 4-7 per label
    if (tid < 64) {
        int c = tid >> 3, f = tid & 7;
        float m = g_s.sums[b][c][f] / g_s.counts[b][c];
        float* base = (f < 4) ? (float*)&smean0[c] : (float*)&smean1[c];
        base[f & 3] = m;
    }
    __syncthreads();

    const int4* g = (const int4*)(tgt + (size_t)b * NPIX);
    const int n0 = blockIdx.x * (2 * P2_THR) + tid;
    const int n1 = n0 + P2_THR;

    // issue all loads for both groups up front (10 LDG.128 in flight)
    int4 lab0 = g[n0];
    int4 lab1 = g[n1];
    uint4 h0[4], h1[4];
#pragma unroll
    for (int k = 0; k < 4; k++) {
        h0[k] = g_h[((size_t)(b * 4 + k)) * NG + n0];
        h1[k] = g_h[((size_t)(b * 4 + k)) * NG + n1];
    }

    float local = 0.f;
#pragma unroll
    for (int grp = 0; grp < 2; grp++) {
        int4 lab4 = grp ? lab1 : lab0;
        const uint4* hh = grp ? h1 : h0;
#pragma unroll
        for (int px = 0; px < 4; px++) {
            int lab = i4get(lab4, px);
            float4 m0 = smean0[lab];
            float4 m1 = smean1[lab];
            float2 q0 = u2f2(px == 0 ? hh[0].x : px == 1 ? hh[0].y : px == 2 ? hh[0].z : hh[0].w);
            float2 q1 = u2f2(px == 0 ? hh[1].x : px == 1 ? hh[1].y : px == 2 ? hh[1].z : hh[1].w);
            float2 q2 = u2f2(px == 0 ? hh[2].x : px == 1 ? hh[2].y : px == 2 ? hh[2].z : hh[2].w);
            float2 q3 = u2f2(px == 0 ? hh[3].x : px == 1 ? hh[3].y : px == 2 ? hh[3].z : hh[3].w);
            float d2 = 0.f, d;
            d = m0.x - q0.x; d2 = fmaf(d, d, d2);
            d = m0.y - q0.y; d2 = fmaf(d, d, d2);
            d = m0.z - q1.x; d2 = fmaf(d, d, d2);
            d = m0.w - q1.y; d2 = fmaf(d, d, d2);
            d = m1.x - q2.x; d2 = fmaf(d, d, d2);
            d = m1.y - q2.y; d2 = fmaf(d, d, d2);
            d = m1.z - q3.x; d2 = fmaf(d, d, d2);
            d = m1.w - q3.y; d2 = fmaf(d, d, d2);
            float t = sqrtf(d2) - 0.5f;            // DELTA_V
            t = fminf(fmaxf(t, 0.f), 100000.f);
            local = fmaf(t, t, local);
        }
    }

#pragma unroll
    for (int o = 16; o > 0; o >>= 1)
        local += __shfl_down_sync(0xffffffffu, local, o);
    __shared__ float sred[8];
    int wid = tid >> 5, lane = tid & 31;
    if (lane == 0) sred[wid] = local;
    __syncthreads();
    if (tid == 0) {
        float s = 0.f;
#pragma unroll
        for (int w = 0; w < 8; w++) s += sred[w];
        atomicAdd(&g_s.dist[b], s);
    }

    // ---- last-block finalize ----
    __shared__ bool s_last;
    __threadfence();
    if (tid == 0) {
        unsigned int t = atomicAdd(&g_s.ticket, 1u);
        s_last = (t == P2_TOTAL - 1);
    }
    __syncthreads();
    if (!s_last) return;

    __shared__ float smu[BN][CC][NF];
    __shared__ float s_ldist[BN], s_lreg[BN], s_inv[BN];
    float cnt_cache = 0.f;
    {
        int bb = tid >> 6, i = (tid >> 3) & 7, j = tid & 7;
        cnt_cache = __ldcg(&g_s.counts[bb][i]);
        smu[bb][i][j] = __ldcg(&g_s.sums[bb][i][j]) / cnt_cache;
    }
    if (tid < BN) { s_ldist[tid] = 0.f; s_lreg[tid] = 0.f; s_inv[tid] = 0.f; }
    __syncthreads();

    {
        int bb = tid >> 6, i = (tid >> 3) & 7, j = tid & 7;
        if (i != j) {
            float d2 = 0.f;
#pragma unroll
            for (int f = 0; f < NF; f++) {
                float d = smu[bb][i][f] - smu[bb][j][f];
                d2 = fmaf(d, d, d2);
            }
            float t = 3.0f - sqrtf(d2);            // 2 * DELTA_D
            t = fminf(fmaxf(t, 0.f), 100000.f);
            atomicAdd(&s_ldist[bb], t * t);
        } else {
            float d2 = 0.f;
#pragma unroll
            for (int f = 0; f < NF; f++)
                d2 = fmaf(smu[bb][i][f], smu[bb][i][f], d2);
            atomicAdd(&s_lreg[bb], sqrtf(d2));
            atomicAdd(&s_inv[bb], 1.0f / cnt_cache);
        }
    }
    __syncthreads();

    if (tid == 0) {
        float total = 0.f;
#pragma unroll
        for (int q = 0; q < BN; q++) {
            float dq = __ldcg(&g_s.dist[q]);
            float l_var  = dq * s_inv[q] / (float)CC;
            float l_dist = s_ldist[q] / (float)(CC * (CC - 1));
            float l_reg  = s_lreg[q] / (float)CC;
            total += l_var + l_dist + 0.001f * l_reg;
        }
        out[0] = total / (float)BN;
    }
    __syncthreads();

    // ---- scratch self-reset for the next graph replay ----
    {
        float* sc = (float*)&g_s;
        // sums (256) + counts (32) + dist (4) = 292 floats, then ticket
        if (tid < 256) sc[tid] = 0.f;
        if (tid < 36)  sc[256 + tid] = 0.f;
        if (tid == 0)  g_s.ticket = 0u;
    }
}

extern "C" void kernel_launch(void* const* d_in, const int* in_sizes, int n_in,
                              void* d_out, int out_size) {
    const float* pred = (const float*)d_in[0];
    const int*   tgt  = (const int*)d_in[1];
    float*       out  = (float*)d_out;
    (void)in_sizes; (void)n_in; (void)out_size;

    dim3 grid1(P1_BX, BN);
    k_pass1<<<grid1, P1_THR>>>(pred, tgt);
    dim3 grid2(P2_BX, BN);
    k_pass2<<<grid2, P2_THR>>>(tgt, out);
}

// round 12
// speedup vs baseline: 1.2573x; 1.2035x over previous
#include <cuda_runtime.h>
#include <cuda_fp16.h>

#define BN   4
#define NF   8
#define CC   8
#define NPIX (512 * 512)
#define NG   (NPIX / 4)          // 65536 pixel-groups per image
#define BPI  37                  // blocks per image
#define NBLK (BN * BPI)          // 148 = one block per SM
#define NGB  ((NG + BPI - 1) / BPI)  // 1772 groups per block
#define NTHR 512

#define SMEM_PRED_BYTES (NGB * 4 * 16)              // 113408: uint4 per pixel
#define SMEM_TOTAL      (SMEM_PRED_BYTES + NGB * 4) // + packed labels

typedef unsigned long long ULL;

struct Scratch {
    float sums[BN][CC][NF];
    float counts[BN][CC];
    float dist[BN];
    unsigned int arrive;
    unsigned int release;
    unsigned int ticket;
};
__device__ Scratch g_s;   // zero-initialized at module load; self-reset each run

__device__ __forceinline__ ULL ffma2(ULL a, ULL b, ULL c) {
    ULL d;
    asm("fma.rn.f32x2 %0, %1, %2, %3;" : "=l"(d) : "l"(a), "l"(b), "l"(c));
    return d;
}
__device__ __forceinline__ ULL fadd2(ULL a, ULL b) {
    ULL d;
    asm("add.rn.f32x2 %0, %1, %2;" : "=l"(d) : "l"(a), "l"(b));
    return d;
}
__device__ __forceinline__ ULL pack2(float lo, float hi) {
    ULL r;
    asm("mov.b64 %0, {%1, %2};" : "=l"(r) : "f"(lo), "f"(hi));
    return r;
}
__device__ __forceinline__ void unpack2(ULL v, float& lo, float& hi) {
    asm("mov.b64 {%0, %1}, %2;" : "=f"(lo), "=f"(hi) : "l"(v));
}
__device__ __forceinline__ float f4get(const float4 v, int i) {
    return i == 0 ? v.x : i == 1 ? v.y : i == 2 ? v.z : v.w;
}
__device__ __forceinline__ int i4get(const int4 v, int i) {
    return i == 0 ? v.x : i == 1 ? v.y : i == 2 ? v.z : v.w;
}
__device__ __forceinline__ unsigned h2u(__half2 h) {
    return *reinterpret_cast<unsigned*>(&h);
}
__device__ __forceinline__ float2 u2f2(unsigned u) {
    return __half22float2(*reinterpret_cast<__half2*>(&u));
}

__global__ void __launch_bounds__(NTHR, 1)
k_all(const float* __restrict__ pred, const int* __restrict__ tgt,
      float* __restrict__ out) {
    extern __shared__ unsigned char smem_raw[];
    uint4*    spred = (uint4*)smem_raw;                          // [NGB*4]
    unsigned* slab  = (unsigned*)(smem_raw + SMEM_PRED_BYTES);   // [NGB]

    const int tid = threadIdx.x;
    const int bx  = blockIdx.x;
    const int img = bx / BPI;
    const int li  = bx % BPI;
    const int g0  = li * NGB;
    const int g1  = (g0 + NGB < NG) ? g0 + NGB : NG;

    const float4* p = (const float4*)(pred + (size_t)img * NF * NPIX);
    const int4*   g = (const int4*)(tgt + (size_t)img * NPIX);
    const ULL ONE2 = 0x3F8000003F800000ull;

    // ================= Phase A: load once, accumulate, cache to smem =======
    ULL acc[CC][4];
    int icnt[CC];
#pragma unroll
    for (int c = 0; c < CC; c++) {
        icnt[c] = 0;
#pragma unroll
        for (int k = 0; k < 4; k++) acc[c][k] = 0ull;
    }

    for (int n = g0 + tid; n < g1; n += NTHR) {
        int4 lab4 = g[n];
        float4 v[NF];
#pragma unroll
        for (int f = 0; f < NF; f++) v[f] = p[f * NG + n];

        int gl = n - g0;
        slab[gl] = (unsigned)(lab4.x) | ((unsigned)(lab4.y) << 8) |
                   ((unsigned)(lab4.z) << 16) | ((unsigned)(lab4.w) << 24);

#pragma unroll
        for (int px = 0; px < 4; px++) {
            int lab = i4get(lab4, px);
            ULL pr[4];
            uint4 hq;
            {
                float a0 = f4get(v[0], px), a1 = f4get(v[1], px);
                float a2 = f4get(v[2], px), a3 = f4get(v[3], px);
                float a4 = f4get(v[4], px), a5 = f4get(v[5], px);
                float a6 = f4get(v[6], px), a7 = f4get(v[7], px);
                pr[0] = pack2(a0, a1); pr[1] = pack2(a2, a3);
                pr[2] = pack2(a4, a5); pr[3] = pack2(a6, a7);
                hq.x = h2u(__floats2half2_rn(a0, a1));
                hq.y = h2u(__floats2half2_rn(a2, a3));
                hq.z = h2u(__floats2half2_rn(a4, a5));
                hq.w = h2u(__floats2half2_rn(a6, a7));
            }
            spred[gl * 4 + px] = hq;
#pragma unroll
            for (int c = 0; c < CC; c++) {
                bool hit = (lab == c);
                ULL m2 = hit ? ONE2 : 0ull;
                icnt[c] += hit;
#pragma unroll
                for (int k = 0; k < 4; k++) acc[c][k] = ffma2(m2, pr[k], acc[c][k]);
            }
        }
    }

    // warp tree-reduce, then cross-warp via static shared
#pragma unroll
    for (int c = 0; c < CC; c++) {
#pragma unroll
        for (int k = 0; k < 4; k++) {
            ULL x = acc[c][k];
#pragma unroll
            for (int o = 16; o > 0; o >>= 1)
                x = fadd2(x, __shfl_down_sync(0xffffffffu, x, o));
            acc[c][k] = x;
        }
        int ic = icnt[c];
#pragma unroll
        for (int o = 16; o > 0; o >>= 1) ic += __shfl_down_sync(0xffffffffu, ic, o);
        icnt[c] = ic;
    }

    __shared__ float sw[16][72];   // 16 warps x (64 sums + 8 counts)
    int wid = tid >> 5, lane = tid & 31;
    if (lane == 0) {
#pragma unroll
        for (int c = 0; c < CC; c++) {
#pragma unroll
            for (int k = 0; k < 4; k++) {
                float lo, hi;
                unpack2(acc[c][k], lo, hi);
                sw[wid][c * NF + 2 * k]     = lo;
                sw[wid][c * NF + 2 * k + 1] = hi;
            }
            sw[wid][64 + c] = (float)icnt[c];
        }
    }
    __syncthreads();
    if (tid < 72) {
        float s = 0.f;
#pragma unroll
        for (int w = 0; w < 16; w++) s += sw[w][tid];
        if (tid < 64)
            atomicAdd(&((float*)g_s.sums)[img * 64 + tid], s);
        else
            atomicAdd(&g_s.counts[img][tid - 64], s);
    }
    __threadfence();
    __syncthreads();

    // ================= Grid barrier (148 resident blocks) ==================
    if (tid == 0) {
        unsigned int a = atomicAdd(&g_s.arrive, 1u);
        if (a == NBLK - 1) {
            atomicExch(&g_s.release, 1u);
        } else {
            volatile unsigned int* rel = &g_s.release;
            while (*rel == 0u) { __nanosleep(64); }
        }
    }
    __syncthreads();
    __threadfence();

    // ================= Phase B: hinge distance from smem-cached pred =======
    __shared__ float smean[NF][CC];
    if (tid < 64) {
        int c = tid & 7, f = tid >> 3;
        smean[f][c] = __ldcg(&g_s.sums[img][c][f]) / __ldcg(&g_s.counts[img][c]);
    }
    __syncthreads();

    float local = 0.f;
    for (int n = g0 + tid; n < g1; n += NTHR) {
        int gl = n - g0;
        unsigned lw = slab[gl];
#pragma unroll
        for (int px = 0; px < 4; px++) {
            uint4 hq = spred[gl * 4 + px];
            int lab = (lw >> (8 * px)) & 0xFF;
            float2 a01 = u2f2(hq.x), a23 = u2f2(hq.y);
            float2 a45 = u2f2(hq.z), a67 = u2f2(hq.w);
            float d2 = 0.f, d;
            d = smean[0][lab] - a01.x; d2 = fmaf(d, d, d2);
            d = smean[1][lab] - a01.y; d2 = fmaf(d, d, d2);
            d = smean[2][lab] - a23.x; d2 = fmaf(d, d, d2);
            d = smean[3][lab] - a23.y; d2 = fmaf(d, d, d2);
            d = smean[4][lab] - a45.x; d2 = fmaf(d, d, d2);
            d = smean[5][lab] - a45.y; d2 = fmaf(d, d, d2);
            d = smean[6][lab] - a67.x; d2 = fmaf(d, d, d2);
            d = smean[7][lab] - a67.y; d2 = fmaf(d, d, d2);
            float t = sqrtf(d2) - 0.5f;          // DELTA_V
            t = fminf(fmaxf(t, 0.f), 100000.f);
            local = fmaf(t, t, local);
        }
    }

#pragma unroll
    for (int o = 16; o > 0; o >>= 1)
        local += __shfl_down_sync(0xffffffffu, local, o);
    __shared__ float sred[16];
    if (lane == 0) sred[wid] = local;
    __syncthreads();
    if (tid == 0) {
        float s = 0.f;
#pragma unroll
        for (int w = 0; w < 16; w++) s += sred[w];
        atomicAdd(&g_s.dist[img], s);
    }

    // ================= Last-block finalize =================================
    __shared__ bool s_last;
    __threadfence();
    if (tid == 0) {
        unsigned int t = atomicAdd(&g_s.ticket, 1u);
        s_last = (t == NBLK - 1);
    }
    __syncthreads();
    if (!s_last) return;

    __shared__ float smu[BN][CC][NF];
    __shared__ float s_ldist[BN], s_lreg[BN], s_inv[BN];
    float cnt_cache = 1.f;
    if (tid < 256) {
        int bb = tid >> 6, i = (tid >> 3) & 7, j = tid & 7;
        cnt_cache = __ldcg(&g_s.counts[bb][i]);
        smu[bb][i][j] = __ldcg(&g_s.sums[bb][i][j]) / cnt_cache;
    }
    if (tid < BN) { s_ldist[tid] = 0.f; s_lreg[tid] = 0.f; s_inv[tid] = 0.f; }
    __syncthreads();

    if (tid < 256) {
        int bb = tid >> 6, i = (tid >> 3) & 7, j = tid & 7;
        if (i != j) {
            float d2 = 0.f;
#pragma unroll
            for (int f = 0; f < NF; f++) {
                float d = smu[bb][i][f] - smu[bb][j][f];
                d2 = fmaf(d, d, d2);
            }
            float t = 3.0f - sqrtf(d2);          // 2 * DELTA_D
            t = fminf(fmaxf(t, 0.f), 100000.f);
            atomicAdd(&s_ldist[bb], t * t);
        } else {
            float d2 = 0.f;
#pragma unroll
            for (int f = 0; f < NF; f++)
                d2 = fmaf(smu[bb][i][f], smu[bb][i][f], d2);
            atomicAdd(&s_lreg[bb], sqrtf(d2));
            atomicAdd(&s_inv[bb], 1.0f / cnt_cache);
        }
    }
    __syncthreads();

    if (tid == 0) {
        float total = 0.f;
#pragma unroll
        for (int q = 0; q < BN; q++) {
            float dq = __ldcg(&g_s.dist[q]);
            float l_var  = dq * s_inv[q] / (float)CC;
            float l_dist = s_ldist[q] / (float)(CC * (CC - 1));
            float l_reg  = s_lreg[q] / (float)CC;
            total += l_var + l_dist + 0.001f * l_reg;
        }
        out[0] = total / (float)BN;
    }
    __syncthreads();

    // ---- scratch self-reset for the next graph replay (race-free: every
    // block has passed the grid barrier and the ticket before we get here) ----
    {
        float* sc = (float*)&g_s;
        if (tid < 292) sc[tid] = 0.f;   // sums(256) + counts(32) + dist(4)
        if (tid == 0) { g_s.arrive = 0u; g_s.release = 0u; g_s.ticket = 0u; }
    }
}

extern "C" void kernel_launch(void* const* d_in, const int* in_sizes, int n_in,
                              void* d_out, int out_size) {
    const float* pred = (const float*)d_in[0];
    const int*   tgt  = (const int*)d_in[1];
    float*       out  = (float*)d_out;
    (void)in_sizes; (void)n_in; (void)out_size;

    static bool attr_done = false;
    if (!attr_done) {
        cudaFuncSetAttribute(k_all, cudaFuncAttributeMaxDynamicSharedMemorySize,
                             SMEM_TOTAL);
        attr_done = true;
    }

    k_all<<<NBLK, NTHR, SMEM_TOTAL>>>(pred, tgt, out);
}

// round 13
// speedup vs baseline: 1.2677x; 1.0083x over previous
#include <cuda_runtime.h>
#include <cuda_fp16.h>

#define BN   4
#define NF   8
#define CC   8
#define NPIX (512 * 512)
#define NG   (NPIX / 4)              // 65536 pixel-groups per image
#define BPI  37                      // blocks per image
#define NBLK (BN * BPI)              // 148 = one block per SM
#define NGB  ((NG + BPI - 1) / BPI)  // 1772 groups per block (last: 1744)
#define NTHR 768
#define NW   (NTHR / 32)             // 24 warps
#define HALF (NTHR / 2)              // 384 threads per feature-half

#define SPRED_HALF_B (NGB * 4 * 8)                     // uint2 per pixel: 56704
#define SLAB_OFF     (2 * SPRED_HALF_B)                // 113408
#define SMEM_TOTAL   (SLAB_OFF + NGB * 4)              // + packed labels

typedef unsigned long long ULL;

struct Scratch {
    float sums[BN][CC][NF];
    float counts[BN][CC];
    float dist[BN];
    unsigned int arrive;
    unsigned int release;
    unsigned int ticket;
};
__device__ Scratch g_s;   // zero-init at load; self-reset at end of every run

__device__ __forceinline__ ULL fadd2(ULL a, ULL b) {
    ULL d;
    asm("add.rn.f32x2 %0, %1, %2;" : "=l"(d) : "l"(a), "l"(b));
    return d;
}
__device__ __forceinline__ ULL pack2(float lo, float hi) {
    ULL r;
    asm("mov.b64 %0, {%1, %2};" : "=l"(r) : "f"(lo), "f"(hi));
    return r;
}
__device__ __forceinline__ void unpack2(ULL v, float& lo, float& hi) {
    asm("mov.b64 {%0, %1}, %2;" : "=f"(lo), "=f"(hi) : "l"(v));
}
// if (lab == c): a0 += p0; a1 += p1; cnt += inc  (setp + 3 predicated adds)
__device__ __forceinline__ void acc_if_eq(ULL& a0, ULL& a1, int& cnt,
                                          int lab, int c, int inc,
                                          ULL p0, ULL p1) {
    asm("{ .reg .pred p; setp.eq.s32 p, %3, %4;\n\t"
        "@p add.rn.f32x2 %0, %0, %6;\n\t"
        "@p add.rn.f32x2 %1, %1, %7;\n\t"
        "@p add.s32 %2, %2, %5; }"
        : "+l"(a0), "+l"(a1), "+r"(cnt)
        : "r"(lab), "r"(c), "r"(inc), "l"(p0), "l"(p1));
}
__device__ __forceinline__ float f4get(const float4 v, int i) {
    return i == 0 ? v.x : i == 1 ? v.y : i == 2 ? v.z : v.w;
}
__device__ __forceinline__ int i4get(const int4 v, int i) {
    return i == 0 ? v.x : i == 1 ? v.y : i == 2 ? v.z : v.w;
}
__device__ __forceinline__ unsigned h2u(float a, float b) {
    __half2 h = __floats2half2_rn(a, b);
    return *reinterpret_cast<unsigned*>(&h);
}
__device__ __forceinline__ float2 u2f2(unsigned u) {
    return __half22float2(*reinterpret_cast<__half2*>(&u));
}

__global__ void __launch_bounds__(NTHR, 1)
k_all(const float* __restrict__ pred, const int* __restrict__ tgt,
      float* __restrict__ out) {
    extern __shared__ unsigned char smem_raw[];
    uint2*    spredA = (uint2*)smem_raw;                         // feats 0-3
    uint2*    spredB = (uint2*)(smem_raw + SPRED_HALF_B);        // feats 4-7
    unsigned* slab   = (unsigned*)(smem_raw + SLAB_OFF);         // labels

    const int tid = threadIdx.x;
    const int bx  = blockIdx.x;
    const int img = bx / BPI;
    const int li  = bx % BPI;
    const int g0  = li * NGB;
    const int g1  = (g0 + NGB < NG) ? g0 + NGB : NG;

    const int halfid = (tid >= HALF) ? 1 : 0;   // 0: feats 0-3, 1: feats 4-7
    const int ht     = tid - halfid * HALF;     // 0..383 within half

    const float4* p = (const float4*)(pred + (size_t)img * NF * NPIX) +
                      (size_t)(halfid * 4) * NG;
    const int4*   g = (const int4*)(tgt + (size_t)img * NPIX);
    uint2* sp = halfid ? spredB : spredA;

    // ====== Phase A: each half streams ALL pixels for its 4 features =======
    ULL acc[CC][2];          // [cluster][feature-pair within this half]
    int cnta = 0, cntb = 0;  // byte-packed pixel counts (used from half A only)
#pragma unroll
    for (int c = 0; c < CC; c++) { acc[c][0] = 0ull; acc[c][1] = 0ull; }

    for (int n = g0 + ht; n < g1; n += HALF) {
        int gl = n - g0;
        int4 lab4 = g[n];
        float4 v0 = p[0 * NG + n];
        float4 v1 = p[1 * NG + n];
        float4 v2 = p[2 * NG + n];
        float4 v3 = p[3 * NG + n];

        if (halfid == 0)
            slab[gl] = (unsigned)(lab4.x) | ((unsigned)(lab4.y) << 8) |
                       ((unsigned)(lab4.z) << 16) | ((unsigned)(lab4.w) << 24);

#pragma unroll
        for (int px = 0; px < 4; px++) {
            float a0 = f4get(v0, px), a1 = f4get(v1, px);
            float a2 = f4get(v2, px), a3 = f4get(v3, px);
            uint2 hq;
            hq.x = h2u(a0, a1);
            hq.y = h2u(a2, a3);
            sp[gl * 4 + px] = hq;

            int lab = i4get(lab4, px);
            ULL pr0 = pack2(a0, a1);
            ULL pr1 = pack2(a2, a3);
#pragma unroll
            for (int c = 0; c < 4; c++)
                acc_if_eq(acc[c][0], acc[c][1], cnta, lab, c, 1 << (8 * c),
                          pr0, pr1);
#pragma unroll
            for (int c = 4; c < 8; c++)
                acc_if_eq(acc[c][0], acc[c][1], cntb, lab, c, 1 << (8 * (c - 4)),
                          pr0, pr1);
        }
    }

    // full 32-lane warp tree-reduce (all lanes in a warp share one half)
    int icnt[CC];
#pragma unroll
    for (int c = 0; c < 4; c++) {
        icnt[c]     = (cnta >> (8 * c)) & 0xFF;
        icnt[c + 4] = (cntb >> (8 * c)) & 0xFF;
    }
#pragma unroll
    for (int c = 0; c < CC; c++) {
#pragma unroll
        for (int k = 0; k < 2; k++) {
            ULL x = acc[c][k];
#pragma unroll
            for (int o = 16; o > 0; o >>= 1)
                x = fadd2(x, __shfl_down_sync(0xffffffffu, x, o));
            acc[c][k] = x;
        }
        int ic = icnt[c];
#pragma unroll
        for (int o = 16; o > 0; o >>= 1) ic += __shfl_down_sync(0xffffffffu, ic, o);
        icnt[c] = ic;
    }

    __shared__ float sw[NW][CC][5];   // 4 half-features + count per cluster
    int wid = tid >> 5, lane = tid & 31;
    if (lane == 0) {
#pragma unroll
        for (int c = 0; c < CC; c++) {
#pragma unroll
            for (int k = 0; k < 2; k++) {
                float lo, hi;
                unpack2(acc[c][k], lo, hi);
                sw[wid][c][2 * k]     = lo;
                sw[wid][c][2 * k + 1] = hi;
            }
            sw[wid][c][4] = (float)icnt[c];
        }
    }
    __syncthreads();
    if (tid < 64) {
        int c = tid >> 3, f = tid & 7;
        float s = 0.f;
        if (f < 4) {
#pragma unroll
            for (int w = 0; w < NW / 2; w++) s += sw[w][c][f];
        } else {
#pragma unroll
            for (int w = NW / 2; w < NW; w++) s += sw[w][c][f - 4];
        }
        atomicAdd(&g_s.sums[img][c][f], s);
    } else if (tid < 72) {
        int c = tid - 64;
        float s = 0.f;
#pragma unroll
        for (int w = 0; w < NW / 2; w++) s += sw[w][c][4];  // counts: half A only
        atomicAdd(&g_s.counts[img][c], s);
    }
    __threadfence();
    __syncthreads();

    // ================= Grid barrier (148 resident blocks) ==================
    if (tid == 0) {
        unsigned int a = atomicAdd(&g_s.arrive, 1u);
        if (a == NBLK - 1) {
            atomicExch(&g_s.release, 1u);
        } else {
            volatile unsigned int* rel = &g_s.release;
            while (*rel == 0u) { __nanosleep(64); }
        }
    }
    __syncthreads();
    __threadfence();

    // ================= Phase B: hinge distance from smem fp16 ==============
    __shared__ float4 smean0[CC];   // features 0-3 per label
    __shared__ float4 smean1[CC];   // features 4-7 per label
    if (tid < 64) {
        int c = tid >> 3, f = tid & 7;
        float m = __ldcg(&g_s.sums[img][c][f]) / __ldcg(&g_s.counts[img][c]);
        float* base = (f < 4) ? (float*)&smean0[c] : (float*)&smean1[c];
        base[f & 3] = m;
    }
    __syncthreads();

    float local = 0.f;
    for (int n = g0 + tid; n < g1; n += NTHR) {
        int gl = n - g0;
        unsigned lw = slab[gl];
#pragma unroll
        for (int px = 0; px < 4; px++) {
            uint2 ha = spredA[gl * 4 + px];
            uint2 hb = spredB[gl * 4 + px];
            int lab = (lw >> (8 * px)) & 0xFF;
            float4 m0 = smean0[lab];
            float4 m1 = smean1[lab];
            float2 q01 = u2f2(ha.x), q23 = u2f2(ha.y);
            float2 q45 = u2f2(hb.x), q67 = u2f2(hb.y);
            float d2 = 0.f, d;
            d = m0.x - q01.x; d2 = fmaf(d, d, d2);
            d = m0.y - q01.y; d2 = fmaf(d, d, d2);
            d = m0.z - q23.x; d2 = fmaf(d, d, d2);
            d = m0.w - q23.y; d2 = fmaf(d, d, d2);
            d = m1.x - q45.x; d2 = fmaf(d, d, d2);
            d = m1.y - q45.y; d2 = fmaf(d, d, d2);
            d = m1.z - q67.x; d2 = fmaf(d, d, d2);
            d = m1.w - q67.y; d2 = fmaf(d, d, d2);
            float t = sqrtf(d2) - 0.5f;           // DELTA_V
            t = fminf(fmaxf(t, 0.f), 100000.f);
            local = fmaf(t, t, local);
        }
    }

#pragma unroll
    for (int o = 16; o > 0; o >>= 1)
        local += __shfl_down_sync(0xffffffffu, local, o);
    __shared__ float sred[NW];
    if (lane == 0) sred[wid] = local;
    __syncthreads();
    if (tid == 0) {
        float s = 0.f;
#pragma unroll
        for (int w = 0; w < NW; w++) s += sred[w];
        atomicAdd(&g_s.dist[img], s);
    }

    // ================= Last-block finalize =================================
    __shared__ bool s_last;
    __threadfence();
    if (tid == 0) {
        unsigned int t = atomicAdd(&g_s.ticket, 1u);
        s_last = (t == NBLK - 1);
    }
    __syncthreads();
    if (!s_last) return;

    __shared__ float smu[BN][CC][NF];
    __shared__ float s_ldist[BN], s_lreg[BN], s_inv[BN];
    float cnt_cache = 1.f;
    if (tid < 256) {
        int bb = tid >> 6, i = (tid >> 3) & 7, j = tid & 7;
        cnt_cache = __ldcg(&g_s.counts[bb][i]);
        smu[bb][i][j] = __ldcg(&g_s.sums[bb][i][j]) / cnt_cache;
    }
    if (tid < BN) { s_ldist[tid] = 0.f; s_lreg[tid] = 0.f; s_inv[tid] = 0.f; }
    __syncthreads();

    if (tid < 256) {
        int bb = tid >> 6, i = (tid >> 3) & 7, j = tid & 7;
        if (i != j) {
            float d2 = 0.f;
#pragma unroll
            for (int f = 0; f < NF; f++) {
                float d = smu[bb][i][f] - smu[bb][j][f];
                d2 = fmaf(d, d, d2);
            }
            float t = 3.0f - sqrtf(d2);           // 2 * DELTA_D
            t = fminf(fmaxf(t, 0.f), 100000.f);
            atomicAdd(&s_ldist[bb], t * t);
        } else {
            float d2 = 0.f;
#pragma unroll
            for (int f = 0; f < NF; f++)
                d2 = fmaf(smu[bb][i][f], smu[bb][i][f], d2);
            atomicAdd(&s_lreg[bb], sqrtf(d2));
            atomicAdd(&s_inv[bb], 1.0f / cnt_cache);
        }
    }
    __syncthreads();

    if (tid == 0) {
        float total = 0.f;
#pragma unroll
        for (int q = 0; q < BN; q++) {
            float dq = __ldcg(&g_s.dist[q]);
            float l_var  = dq * s_inv[q] / (float)CC;
            float l_dist = s_ldist[q] / (float)(CC * (CC - 1));
            float l_reg  = s_lreg[q] / (float)CC;
            total += l_var + l_dist + 0.001f * l_reg;
        }
        out[0] = total / (float)BN;
    }
    __syncthreads();

    // ---- scratch self-reset for the next graph replay ----
    {
        float* sc = (float*)&g_s;
        if (tid < 292) sc[tid] = 0.f;   // sums(256) + counts(32) + dist(4)
        if (tid == 0) { g_s.arrive = 0u; g_s.release = 0u; g_s.ticket = 0u; }
    }
}

extern "C" void kernel_launch(void* const* d_in, const int* in_sizes, int n_in,
                              void* d_out, int out_size) {
    const float* pred = (const float*)d_in[0];
    const int*   tgt  = (const int*)d_in[1];
    float*       out  = (float*)d_out;
    (void)in_sizes; (void)n_in; (void)out_size;

    static bool attr_done = false;
    if (!attr_done) {
        cudaFuncSetAttribute(k_all, cudaFuncAttributeMaxDynamicSharedMemorySize,
                             SMEM_TOTAL);
        attr_done = true;
    }

    k_all<<<NBLK, NTHR, SMEM_TOTAL>>>(pred, tgt, out);
}